// round 13
// baseline (speedup 1.0000x reference)
#include <cuda_runtime.h>
#include <cuda_fp16.h>

#define S_LEN 2048
#define BATCH 4
#define HEADS 16
#define DH 64
#define DIN 1024
#define M_TOT (BATCH * S_LEN)  // 8192

// ---------------- scratch (allocation-free) — fp16 ----------------
__device__ __half g_xh[M_TOT * DIN];                 // x fp16
__device__ __half g_wqt[HEADS * DH * DIN];           // W^T fp16: [h][e][k]
__device__ __half g_wkt[HEADS * DH * DIN];
__device__ __half g_wvt[HEADS * DH * DIN];
__device__ __half g_wot[DH * DIN];                   // [n=64][k=1024]
__device__ __half g_q[BATCH * HEADS * S_LEN * DH];   // 0.125*log2e scale folded
__device__ __half g_k[BATCH * HEADS * S_LEN * DH];
__device__ __half g_v[BATCH * HEADS * S_LEN * DH];   // natural [s][e]
__device__ __half g_attn[M_TOT * HEADS * DH];        // [m][h*64+e]

// ---------------- helpers ----------------
__device__ __forceinline__ unsigned packh2(float lo, float hi) {
    __half2 h = __floats2half2_rn(lo, hi);
    return *(unsigned*)&h;
}
__device__ __forceinline__ float ex2(float x) {
    float r;
    asm("ex2.approx.f32 %0, %1;" : "=f"(r) : "f"(x));
    return r;
}
__device__ __forceinline__ void mma_f16(float* c, const unsigned* a,
                                        unsigned b0, unsigned b1) {
    asm volatile(
        "mma.sync.aligned.m16n8k16.row.col.f32.f16.f16.f32 "
        "{%0,%1,%2,%3}, {%4,%5,%6,%7}, {%8,%9}, {%0,%1,%2,%3};\n"
        : "+f"(c[0]), "+f"(c[1]), "+f"(c[2]), "+f"(c[3])
        : "r"(a[0]), "r"(a[1]), "r"(a[2]), "r"(a[3]), "r"(b0), "r"(b1));
}
__device__ __forceinline__ void ldsm4(unsigned& r0, unsigned& r1,
                                      unsigned& r2, unsigned& r3, unsigned a) {
    asm volatile("ldmatrix.sync.aligned.m8n8.x4.shared.b16 {%0,%1,%2,%3}, [%4];"
                 : "=r"(r0), "=r"(r1), "=r"(r2), "=r"(r3) : "r"(a));
}
__device__ __forceinline__ void ldsm4t(unsigned& r0, unsigned& r1,
                                       unsigned& r2, unsigned& r3, unsigned a) {
    asm volatile("ldmatrix.sync.aligned.m8n8.x4.trans.shared.b16 {%0,%1,%2,%3}, [%4];"
                 : "=r"(r0), "=r"(r1), "=r"(r2), "=r"(r3) : "r"(a));
}
__device__ __forceinline__ void cp16(unsigned saddr, const void* gptr) {
    asm volatile("cp.async.ca.shared.global [%0], [%1], 16;\n"
                 :: "r"(saddr), "l"(gptr));
}
__device__ __forceinline__ unsigned saddr_of(const void* p) {
    return (unsigned)__cvta_generic_to_shared(p);
}
#define CP_COMMIT() asm volatile("cp.async.commit_group;\n" ::: "memory")
#define CP_WAIT1()  asm volatile("cp.async.wait_group 1;\n" ::: "memory")
#define CP_WAIT0()  asm volatile("cp.async.wait_group 0;\n" ::: "memory")

#define LOG2E 1.44269504088896f

// ======================= pre-convert =======================
__global__ __launch_bounds__(256) void x_to_h(
    const float4* __restrict__ src, uint2* __restrict__ dst, int n4)
{
    int i = blockIdx.x * blockDim.x + threadIdx.x;
    if (i < n4) {
        float4 v = src[i];
        dst[i] = make_uint2(packh2(v.x, v.y), packh2(v.z, v.w));
    }
}

// W [h][k=1024][e=64] fp32 -> Wt [h][e=64][k=1024] fp16. grid (16 ktiles, h, 3).
__global__ __launch_bounds__(256) void w_transpose3(
    const float* __restrict__ Wq, const float* __restrict__ Wk,
    const float* __restrict__ Wv)
{
    __shared__ float S[64][65];
    const int h = blockIdx.y, k0 = blockIdx.x * 64, p = blockIdx.z;
    const float* W = (p == 0) ? Wq : (p == 1) ? Wk : Wv;
    __half* Wt = (p == 0) ? g_wqt : (p == 1) ? g_wkt : g_wvt;
    const int tid = threadIdx.x;
    {
        int r = tid >> 2, e0 = (tid & 3) * 16;
        const float* src = W + ((size_t)h * DIN + k0 + r) * DH + e0;
        #pragma unroll
        for (int i = 0; i < 4; i++) {
            float4 v = *(const float4*)(src + 4 * i);
            S[r][e0 + 4 * i + 0] = v.x; S[r][e0 + 4 * i + 1] = v.y;
            S[r][e0 + 4 * i + 2] = v.z; S[r][e0 + 4 * i + 3] = v.w;
        }
    }
    __syncthreads();
    {
        int e = tid >> 2, c0 = (tid & 3) * 16;
        unsigned buf[8];
        #pragma unroll
        for (int i = 0; i < 8; i++)
            buf[i] = packh2(S[c0 + 2 * i][e], S[c0 + 2 * i + 1][e]);
        __half* dst = Wt + ((size_t)h * DH + e) * DIN + k0 + c0;
        *(uint4*)dst = make_uint4(buf[0], buf[1], buf[2], buf[3]);
        *(uint4*)(dst + 8) = make_uint4(buf[4], buf[5], buf[6], buf[7]);
    }
}

__global__ __launch_bounds__(256) void w_transpose1(
    const float* __restrict__ W)
{
    __shared__ float S[64][65];
    const int k0 = blockIdx.x * 64;
    const int tid = threadIdx.x;
    {
        int r = tid >> 2, e0 = (tid & 3) * 16;
        const float* src = W + (size_t)(k0 + r) * DH + e0;
        #pragma unroll
        for (int i = 0; i < 4; i++) {
            float4 v = *(const float4*)(src + 4 * i);
            S[r][e0 + 4 * i + 0] = v.x; S[r][e0 + 4 * i + 1] = v.y;
            S[r][e0 + 4 * i + 2] = v.z; S[r][e0 + 4 * i + 3] = v.w;
        }
    }
    __syncthreads();
    {
        int e = tid >> 2, c0 = (tid & 3) * 16;
        unsigned buf[8];
        #pragma unroll
        for (int i = 0; i < 8; i++)
            buf[i] = packh2(S[c0 + 2 * i][e], S[c0 + 2 * i + 1][e]);
        __half* dst = g_wot + (size_t)e * DIN + k0 + c0;
        *(uint4*)dst = make_uint4(buf[0], buf[1], buf[2], buf[3]);
        *(uint4*)(dst + 8) = make_uint4(buf[4], buf[5], buf[6], buf[7]);
    }
}

// ======================= QKV projection (fp16 mma, 3-stage cp.async) =============
// grid (64 m-tiles, 8 head-pairs, 3); block 256 (8 warps 4M x 2N), warp 32x64.
#define STR 36                     // word stride (== 4 mod 32)
#define QA_W (128 * STR)           // 4608 words per buffer
#define QB_W (128 * STR)
#define QKV_SMEM ((QA_W + QB_W) * 3 * 4)   // 110592 B

__global__ __launch_bounds__(256, 2) void qkv_gemm(
    const float* __restrict__ bq, const float* __restrict__ bk,
    const float* __restrict__ bv)
{
    extern __shared__ unsigned qsm[];
    unsigned* As = qsm;                  // [3][128][36]
    unsigned* Bs = qsm + 3 * QA_W;       // [3][128][36]

    const int p = blockIdx.z, hp = blockIdx.y;
    const __half* Wt; const float* bias; __half* out; float sc;
    if (p == 0)      { Wt = g_wqt; bias = bq; out = g_q; sc = 0.125f * LOG2E; }
    else if (p == 1) { Wt = g_wkt; bias = bk; out = g_k; sc = 1.0f; }
    else             { Wt = g_wvt; bias = bv; out = g_v; sc = 1.0f; }

    const int tid = threadIdx.x, w = tid >> 5, lane = tid & 31;
    const int g = lane >> 2, t = lane & 3;
    const int wm = w >> 1, wn = w & 1;
    const int m0 = blockIdx.x * 128;

    const int a_row = lane & 15, a_kw = (lane >> 4) << 2;
    const int b_row = (lane & 7) | ((lane & 16) >> 1);
    const int b_kw  = (lane & 8) ? 4 : 0;

    const int lr = tid >> 1, lc = (tid & 1) * 32;
    const __half* xA = g_xh + (size_t)(m0 + lr) * DIN + lc;
    const __half* WB = Wt + ((size_t)(2 * hp + (lr >> 6)) * DH + (lr & 63)) * DIN + lc;

    const unsigned sA = saddr_of(As), sB = saddr_of(Bs);
    auto issue = [&](int k0, int buf) {
        unsigned da = sA + (buf * QA_W + lr * STR + (lc >> 1)) * 4;
        unsigned db = sB + (buf * QB_W + lr * STR + (lc >> 1)) * 4;
        #pragma unroll
        for (int i = 0; i < 4; i++) cp16(da + 16 * i, xA + k0 + 8 * i);
        #pragma unroll
        for (int i = 0; i < 4; i++) cp16(db + 16 * i, WB + k0 + 8 * i);
        CP_COMMIT();
    };

    const unsigned aoff = ((32 * wm + a_row) * STR + a_kw) * 4;
    const unsigned boff = ((64 * wn + b_row) * STR + b_kw) * 4;

    float acc[2][8][4] = {};
    const int NT = DIN / 64;   // 16

    issue(0, 0);
    issue(64, 1);
    int buf = 0;
    for (int tt = 0; tt < NT; tt++) {
        if (tt + 1 < NT) { CP_WAIT1(); } else { CP_WAIT0(); }
        __syncthreads();
        if (tt + 2 < NT) issue((tt + 2) * 64, (tt + 2) % 3);

        unsigned ab = sA + buf * QA_W * 4;
        unsigned bb = sB + buf * QB_W * 4;
        #pragma unroll
        for (int ks = 0; ks < 4; ks++) {
            unsigned a[2][4];
            ldsm4(a[0][0], a[0][1], a[0][2], a[0][3], ab + aoff + 32 * ks);
            ldsm4(a[1][0], a[1][1], a[1][2], a[1][3],
                  ab + aoff + (16 * STR) * 4 + 32 * ks);
            #pragma unroll
            for (int nfp = 0; nfp < 4; nfp++) {
                unsigned b0, b1, b2, b3;
                ldsm4(b0, b1, b2, b3, bb + boff + (16 * nfp * STR) * 4 + 32 * ks);
                mma_f16(acc[0][2 * nfp],     a[0], b0, b1);
                mma_f16(acc[1][2 * nfp],     a[1], b0, b1);
                mma_f16(acc[0][2 * nfp + 1], a[0], b2, b3);
                mma_f16(acc[1][2 * nfp + 1], a[1], b2, b3);
            }
        }
        __syncthreads();   // all warps done reading buf before it is refilled
        buf = (buf + 1) % 3;
    }

    // epilogue: bias (+scale) -> fp16 pairs -> scatter [B,H,S,64]
    const int head = 2 * hp + wn;
    const float* bp = bias + head * DH;
    #pragma unroll
    for (int mi = 0; mi < 2; mi++) {
        #pragma unroll
        for (int nf = 0; nf < 8; nf++) {
            int e = 8 * nf + 2 * t;
            float be0 = bp[e], be1 = bp[e + 1];
            int row = m0 + 32 * wm + 16 * mi + g;
            #pragma unroll
            for (int rr = 0; rr < 2; rr++) {
                int m = row + 8 * rr;
                int bb2 = m >> 11, s = m & 2047;
                size_t base = (((size_t)bb2 * HEADS + head) * S_LEN + s) * DH + e;
                *(unsigned*)(out + base) =
                    packh2((acc[mi][nf][2 * rr] + be0) * sc,
                           (acc[mi][nf][2 * rr + 1] + be1) * sc);
            }
        }
    }
}

// ======================= Flash attention (fp16 mma, FA2, exp2 domain) ============
// grid (16 q-tiles, 64 bh); block 128 (4 warps x 32 q-rows), 3 CTAs/SM.
// Q re-loaded from smem per kt (frees regs); P register-passed; scores in log2.
#define K_W (64 * STR)     // 2304 words per buffer
#define V_W (64 * STR)
#define P_W (128 * STR)    // Q staging (persistent)
#define ATT_SMEM (((K_W + V_W) * 2 + P_W) * 4)   // 55296 B

__global__ __launch_bounds__(128, 3) void flash_kernel()
{
    extern __shared__ unsigned fsm[];
    unsigned* Ks = fsm;                     // [2][64][36]
    unsigned* Vs = fsm + 2 * K_W;           // [2][64][36] natural [kv][e]
    unsigned* Ps = fsm + 2 * (K_W + V_W);   // Q staging (never overwritten)

    const int tid = threadIdx.x, w = tid >> 5, lane = tid & 31;
    const int g = lane >> 2, t = lane & 3;
    const int qt = (int)(gridDim.x - 1 - blockIdx.x);
    const int bh = blockIdx.y;
    const size_t base = (size_t)bh * S_LEN * DH;
    const int qrow0 = qt * 128;

    const int a_row = lane & 15, a_kw = (lane >> 4) << 2;
    const int b_row = (lane & 7) | ((lane & 16) >> 1);
    const int b_kw  = (lane & 8) ? 4 : 0;
    const int v_row = lane & 15, v_ew = (lane & 16) >> 2;

    const unsigned sK = saddr_of(Ks), sV = saddr_of(Vs), sP = saddr_of(Ps);

    const int lr = tid >> 1, lc = (tid & 1) * 32;
    auto issue_kv = [&](int kt, int buf) {
        unsigned dk = sK + (buf * K_W + lr * STR + (lc >> 1)) * 4;
        unsigned dv = sV + (buf * V_W + lr * STR + (lc >> 1)) * 4;
        const __half* kg = g_k + base + (size_t)(kt * 64 + lr) * DH + lc;
        const __half* vg = g_v + base + (size_t)(kt * 64 + lr) * DH + lc;
        #pragma unroll
        for (int i = 0; i < 4; i++) cp16(dk + 16 * i, kg + 8 * i);
        #pragma unroll
        for (int i = 0; i < 4; i++) cp16(dv + 16 * i, vg + 8 * i);
        CP_COMMIT();
    };

    issue_kv(0, 0);
    // stage Q (fp16, 0.125*log2e folded) via cp.async
    {
        unsigned dq = sP + (tid * STR) * 4;
        const __half* qg = g_q + base + (size_t)(qrow0 + tid) * DH;
        #pragma unroll
        for (int i = 0; i < 8; i++) cp16(dq + 16 * i, qg + 8 * i);
        CP_COMMIT();
    }
    CP_WAIT0();
    __syncthreads();

    const unsigned qbase0 = sP + (((32 * w + a_row) * STR + a_kw) * 4);
    const unsigned qbase1 = qbase0 + (16 * STR) * 4;

    float m_i[4] = {-1e30f, -1e30f, -1e30f, -1e30f};
    float l_i[4] = {0.f, 0.f, 0.f, 0.f};
    float o[2][8][4] = {};

    const int ktmax = 2 * qt + 1;
    for (int kt = 0; kt <= ktmax; kt++) {
        if (kt > 0) { CP_WAIT0(); __syncthreads(); }
        if (kt < ktmax) issue_kv(kt + 1, (kt + 1) & 1);
        unsigned kb = sK + (kt & 1) * K_W * 4;
        unsigned vb = sV + (kt & 1) * V_W * 4;

        // S = Q K^T (scores arrive in log2 domain)
        float c_[2][8][4] = {};
        #pragma unroll
        for (int ks = 0; ks < 4; ks++) {
            unsigned q0[4], q1[4];
            ldsm4(q0[0], q0[1], q0[2], q0[3], qbase0 + 32 * ks);
            ldsm4(q1[0], q1[1], q1[2], q1[3], qbase1 + 32 * ks);
            #pragma unroll
            for (int nfp = 0; nfp < 4; nfp++) {
                unsigned b0, b1, b2, b3;
                ldsm4(b0, b1, b2, b3,
                      kb + (((16 * nfp + b_row) * STR + b_kw) * 4) + 32 * ks);
                mma_f16(c_[0][2 * nfp],     q0, b0, b1);
                mma_f16(c_[1][2 * nfp],     q1, b0, b1);
                mma_f16(c_[0][2 * nfp + 1], q0, b2, b3);
                mma_f16(c_[1][2 * nfp + 1], q1, b2, b3);
            }
        }

        // causal mask (diagonal-adjacent tiles only)
        if (kt >= 2 * qt) {
            int colbase = kt * 64;
            #pragma unroll
            for (int mi = 0; mi < 2; mi++) {
                int r0 = qrow0 + 32 * w + 16 * mi + g;
                #pragma unroll
                for (int nf = 0; nf < 8; nf++) {
                    int col = colbase + 8 * nf + 2 * t;
                    if (col     > r0)     c_[mi][nf][0] = -1e30f;
                    if (col + 1 > r0)     c_[mi][nf][1] = -1e30f;
                    if (col     > r0 + 8) c_[mi][nf][2] = -1e30f;
                    if (col + 1 > r0 + 8) c_[mi][nf][3] = -1e30f;
                }
            }
        }

        // online softmax in log2 domain (ex2 instead of exp)
        float alpha[4];
        #pragma unroll
        for (int mi = 0; mi < 2; mi++)
            #pragma unroll
            for (int hh = 0; hh < 2; hh++) {
                int rr = 2 * mi + hh;
                float mx = -1e30f;
                #pragma unroll
                for (int nf = 0; nf < 8; nf++)
                    mx = fmaxf(mx, fmaxf(c_[mi][nf][2 * hh], c_[mi][nf][2 * hh + 1]));
                mx = fmaxf(mx, __shfl_xor_sync(0xffffffffu, mx, 1));
                mx = fmaxf(mx, __shfl_xor_sync(0xffffffffu, mx, 2));
                float m_new = fmaxf(m_i[rr], mx);
                alpha[rr] = ex2(m_i[rr] - m_new);
                float sum = 0.f;
                #pragma unroll
                for (int nf = 0; nf < 8; nf++) {
                    float p0 = ex2(c_[mi][nf][2 * hh] - m_new);
                    float p1 = ex2(c_[mi][nf][2 * hh + 1] - m_new);
                    c_[mi][nf][2 * hh] = p0; c_[mi][nf][2 * hh + 1] = p1;
                    sum += p0 + p1;
                }
                sum += __shfl_xor_sync(0xffffffffu, sum, 1);
                sum += __shfl_xor_sync(0xffffffffu, sum, 2);
                l_i[rr] = l_i[rr] * alpha[rr] + sum;
                m_i[rr] = m_new;
            }

        // rescale O
        #pragma unroll
        for (int mi = 0; mi < 2; mi++)
            #pragma unroll
            for (int nf = 0; nf < 8; nf++) {
                o[mi][nf][0] *= alpha[2 * mi];     o[mi][nf][1] *= alpha[2 * mi];
                o[mi][nf][2] *= alpha[2 * mi + 1]; o[mi][nf][3] *= alpha[2 * mi + 1];
            }

        // O += P V — P packed from accumulator regs into A-fragments directly
        #pragma unroll
        for (int ks = 0; ks < 4; ks++) {
            unsigned a[2][4];
            #pragma unroll
            for (int mi = 0; mi < 2; mi++) {
                a[mi][0] = packh2(c_[mi][2 * ks][0],     c_[mi][2 * ks][1]);
                a[mi][1] = packh2(c_[mi][2 * ks][2],     c_[mi][2 * ks][3]);
                a[mi][2] = packh2(c_[mi][2 * ks + 1][0], c_[mi][2 * ks + 1][1]);
                a[mi][3] = packh2(c_[mi][2 * ks + 1][2], c_[mi][2 * ks + 1][3]);
            }
            #pragma unroll
            for (int nfp = 0; nfp < 4; nfp++) {
                unsigned b0, b1, b2, b3;
                ldsm4t(b0, b1, b2, b3,
                       vb + (((16 * ks + v_row) * STR + 8 * nfp + v_ew) * 4));
                mma_f16(o[0][2 * nfp],     a[0], b0, b1);
                mma_f16(o[1][2 * nfp],     a[1], b0, b1);
                mma_f16(o[0][2 * nfp + 1], a[0], b2, b3);
                mma_f16(o[1][2 * nfp + 1], a[1], b2, b3);
            }
        }
    }

    // epilogue: normalize -> fp16 -> concat-head write [m][h*64+e]
    const int b = bh >> 4, h = bh & 15;
    #pragma unroll
    for (int mi = 0; mi < 2; mi++) {
        float inv0 = 1.f / l_i[2 * mi], inv1 = 1.f / l_i[2 * mi + 1];
        int row = qrow0 + 32 * w + 16 * mi + g;
        #pragma unroll
        for (int nf = 0; nf < 8; nf++) {
            int e = 8 * nf + 2 * t;
            size_t i0 = ((size_t)(b * S_LEN + row)) * (HEADS * DH) + h * DH + e;
            size_t i1 = ((size_t)(b * S_LEN + row + 8)) * (HEADS * DH) + h * DH + e;
            *(unsigned*)(g_attn + i0) = packh2(o[mi][nf][0] * inv0, o[mi][nf][1] * inv0);
            *(unsigned*)(g_attn + i1) = packh2(o[mi][nf][2] * inv1, o[mi][nf][3] * inv1);
        }
    }
}

// ======================= Output projection (fp16 mma + ldmatrix) =================
#define OA_W (128 * STR)
#define OB_W (64 * STR)
#define OUT_SMEM ((OA_W + OB_W) * 2 * 4)   // 55296 B

__global__ __launch_bounds__(256, 2) void out_gemm(
    const float* __restrict__ bo, float* __restrict__ outp)
{
    extern __shared__ unsigned osm[];
    unsigned* As = osm;                 // [2][128][36]
    unsigned* Bs = osm + 2 * OA_W;      // [2][64][36]

    const int tid = threadIdx.x, w = tid >> 5, lane = tid & 31;
    const int g = lane >> 2, t = lane & 3;
    const int wm = w >> 1, wn = w & 1;
    const int m0 = blockIdx.x * 128;

    const int a_row = lane & 15, a_kw = (lane >> 4) << 2;
    const int b_row = (lane & 7) | ((lane & 16) >> 1);
    const int b_kw  = (lane & 8) ? 4 : 0;

    const unsigned sA = saddr_of(As), sB = saddr_of(Bs);
    const int lar = tid >> 1, lac = (tid & 1) * 32;
    const int lbr = tid >> 2, lbc = (tid & 3) * 16;
    const __half* xA = g_attn + (size_t)(m0 + lar) * DIN + lac;
    const __half* WB = g_wot + (size_t)lbr * DIN + lbc;

    auto issue = [&](int k0, int buf) {
        unsigned da = sA + (buf * OA_W + lar * STR + (lac >> 1)) * 4;
        unsigned db = sB + (buf * OB_W + lbr * STR + (lbc >> 1)) * 4;
        #pragma unroll
        for (int i = 0; i < 4; i++) cp16(da + 16 * i, xA + k0 + 8 * i);
        #pragma unroll
        for (int i = 0; i < 2; i++) cp16(db + 16 * i, WB + k0 + 8 * i);
        CP_COMMIT();
    };

    const unsigned aoff = ((32 * wm + a_row) * STR + a_kw) * 4;
    const unsigned boff = ((32 * wn + b_row) * STR + b_kw) * 4;

    float acc[2][4][4] = {};
    const int NT = DIN / 64;

    issue(0, 0);
    for (int tt = 0; tt < NT; tt++) {
        CP_WAIT0();
        __syncthreads();
        if (tt + 1 < NT) issue((tt + 1) * 64, (tt + 1) & 1);

        unsigned ab = sA + (tt & 1) * OA_W * 4;
        unsigned bb = sB + (tt & 1) * OB_W * 4;
        #pragma unroll
        for (int ks = 0; ks < 4; ks++) {
            unsigned a[2][4];
            ldsm4(a[0][0], a[0][1], a[0][2], a[0][3], ab + aoff + 32 * ks);
            ldsm4(a[1][0], a[1][1], a[1][2], a[1][3],
                  ab + aoff + (16 * STR) * 4 + 32 * ks);
            #pragma unroll
            for (int nfp = 0; nfp < 2; nfp++) {
                unsigned b0, b1, b2, b3;
                ldsm4(b0, b1, b2, b3, bb + boff + (16 * nfp * STR) * 4 + 32 * ks);
                mma_f16(acc[0][2 * nfp],     a[0], b0, b1);
                mma_f16(acc[1][2 * nfp],     a[1], b0, b1);
                mma_f16(acc[0][2 * nfp + 1], a[0], b2, b3);
                mma_f16(acc[1][2 * nfp + 1], a[1], b2, b3);
            }
        }
    }

    #pragma unroll
    for (int mi = 0; mi < 2; mi++)
        #pragma unroll
        for (int nf = 0; nf < 4; nf++) {
            int e = 32 * wn + 8 * nf + 2 * t;
            float be0 = bo[e], be1 = bo[e + 1];
            int row = m0 + 32 * wm + 16 * mi + g;
            #pragma unroll
            for (int rr = 0; rr < 2; rr++) {
                int m = row + 8 * rr;
                *(float2*)(outp + (size_t)m * DH + e) =
                    make_float2(acc[mi][nf][2 * rr] + be0,
                                acc[mi][nf][2 * rr + 1] + be1);
            }
        }
}

// ======================= launch =======================
extern "C" void kernel_launch(void* const* d_in, const int* in_sizes, int n_in,
                              void* d_out, int out_size)
{
    const float* x  = (const float*)d_in[0];
    const float* Wq = (const float*)d_in[1];
    const float* bq = (const float*)d_in[2];
    const float* Wk = (const float*)d_in[3];
    const float* bk = (const float*)d_in[4];
    const float* Wv = (const float*)d_in[5];
    const float* bv = (const float*)d_in[6];
    const float* Wo = (const float*)d_in[7];
    const float* bo = (const float*)d_in[8];
    float* outp = (float*)d_out;

    cudaFuncSetAttribute(qkv_gemm,
                         cudaFuncAttributeMaxDynamicSharedMemorySize, QKV_SMEM);
    cudaFuncSetAttribute(flash_kernel,
                         cudaFuncAttributeMaxDynamicSharedMemorySize, ATT_SMEM);
    cudaFuncSetAttribute(out_gemm,
                         cudaFuncAttributeMaxDynamicSharedMemorySize, OUT_SMEM);

    void* p_xh;
    cudaGetSymbolAddress(&p_xh, g_xh);

    const int NX4 = M_TOT * DIN / 4;
    x_to_h<<<NX4 / 256, 256>>>((const float4*)x, (uint2*)p_xh, NX4);
    w_transpose3<<<dim3(DIN / 64, HEADS, 3), 256>>>(Wq, Wk, Wv);
    w_transpose1<<<dim3(DIN / 64, 1), 256>>>(Wo);

    dim3 g1(M_TOT / 128, HEADS / 2, 3);
    qkv_gemm<<<g1, 256, QKV_SMEM>>>(bq, bk, bv);

    dim3 g2(S_LEN / 128, BATCH * HEADS);
    flash_kernel<<<g2, 128, ATT_SMEM>>>();

    out_gemm<<<M_TOT / 128, 256, OUT_SMEM>>>(bo, outp);
}